// round 4
// baseline (speedup 1.0000x reference)
#include <cuda_runtime.h>
#include <cuda_fp16.h>
#include <cstdint>

#define D_MODEL 1024
#define D_DICT  16384
#define NTOK    8192
#define TOPK    32

#define CAND_CAP 160
#define NARROW   44
#define CAND2    96
#define THR_SIG  2.8f

// ---------------- scratch (static device globals; no allocations) ----------------
__device__ __half g_xh[NTOK * D_MODEL];            // 16 MB  x in fp16
__device__ __half g_wh[D_DICT * D_MODEL];          // 32 MB  W_enc in fp16
__device__ __half g_wt[(size_t)D_DICT * D_MODEL];  // 32 MB  W_dec^T in fp16 [f][d]
__device__ float  g_thr[NTOK];
__device__ unsigned g_cand[NTOK * CAND_CAP];       // (fp16 abs bits << 16) | col
__device__ int    g_cnt[NTOK];
__device__ int    g_selidx[NTOK * TOPK];
__device__ float  g_selval[NTOK * TOPK];

// ---------------- utility kernels ----------------
__global__ void zero_kernel(float4* p, int n4) {
    float4 z = make_float4(0.f, 0.f, 0.f, 0.f);
    int tid0 = blockIdx.x * blockDim.x + threadIdx.x;
    if (tid0 < NTOK / 4) reinterpret_cast<int4*>(g_cnt)[tid0] = make_int4(0, 0, 0, 0);
    for (int i = tid0; i < n4; i += gridDim.x * blockDim.x)
        p[i] = z;
}

__global__ void cvt_kernel(const float2* __restrict__ s, int n2, int mode) {
    __half2* d = mode ? reinterpret_cast<__half2*>(g_wh) : reinterpret_cast<__half2*>(g_xh);
    for (int i = blockIdx.x * blockDim.x + threadIdx.x; i < n2; i += gridDim.x * blockDim.x)
        d[i] = __float22half2_rn(s[i]);
}

__global__ void rownorm_kernel(const float* __restrict__ x) {
    int row = blockIdx.x * 8 + (threadIdx.x >> 5);
    int lane = threadIdx.x & 31;
    const float4* xr = reinterpret_cast<const float4*>(x + (size_t)row * D_MODEL);
    float ss = 0.f;
#pragma unroll
    for (int j = 0; j < 8; ++j) {
        float4 v = xr[lane + j * 32];
        ss += v.x * v.x + v.y * v.y + v.z * v.z + v.w * v.w;
    }
#pragma unroll
    for (int off = 16; off; off >>= 1) ss += __shfl_down_sync(0xffffffffu, ss, off);
    if (lane == 0) g_thr[row] = THR_SIG * sqrtf(ss) * (1.0f / 32.0f);
}

__global__ void transpose_kernel(const float* __restrict__ src) {
    __shared__ float tile[32][33];
    int fx = blockIdx.x * 32 + threadIdx.x;
    int dy = blockIdx.y * 32 + threadIdx.y;
#pragma unroll
    for (int j = 0; j < 32; j += 8)
        tile[threadIdx.y + j][threadIdx.x] = src[(size_t)(dy + j) * D_DICT + fx];
    __syncthreads();
    int dx = blockIdx.y * 32 + threadIdx.x;
    int fy = blockIdx.x * 32 + threadIdx.y;
#pragma unroll
    for (int j = 0; j < 32; j += 8)
        g_wt[(size_t)(fy + j) * D_MODEL + dx] = __float2half_rn(tile[threadIdx.x][threadIdx.y + j]);
}

// ---------------- fp16 mma.sync encoder GEMM, 128x256 CTA / 64x64 warp ----------------
#define BM 128
#define BN 256
#define BK 64
#define BKP 72   // padded K stride (halfs): 144B rows, conflict-free ldmatrix

__device__ __forceinline__ void cp16(uint32_t s, const void* g) {
    asm volatile("cp.async.cg.shared.global [%0], [%1], 16;\n" :: "r"(s), "l"(g));
}
__device__ __forceinline__ void cp_commit() { asm volatile("cp.async.commit_group;\n"); }
__device__ __forceinline__ void cp_wait0()  { asm volatile("cp.async.wait_group 0;\n"); }
__device__ __forceinline__ void cp_wait1()  { asm volatile("cp.async.wait_group 1;\n"); }

__device__ __forceinline__ void ldsm4(uint32_t& r0, uint32_t& r1, uint32_t& r2, uint32_t& r3, uint32_t a) {
    asm volatile("ldmatrix.sync.aligned.m8n8.x4.shared.b16 {%0,%1,%2,%3}, [%4];\n"
                 : "=r"(r0), "=r"(r1), "=r"(r2), "=r"(r3) : "r"(a));
}
__device__ __forceinline__ void mma16816(float* c, const uint32_t* a, const uint32_t* b) {
    asm volatile("mma.sync.aligned.m16n8k16.row.col.f32.f16.f16.f32 "
                 "{%0,%1,%2,%3},{%4,%5,%6,%7},{%8,%9},{%0,%1,%2,%3};\n"
                 : "+f"(c[0]), "+f"(c[1]), "+f"(c[2]), "+f"(c[3])
                 : "r"(a[0]), "r"(a[1]), "r"(a[2]), "r"(a[3]), "r"(b[0]), "r"(b[1]));
}

__device__ __forceinline__ void push_cand(int row, int col, float v, float th) {
    if (fabsf(v) >= th) {
        unsigned hb = __half_as_ushort(__float2half_rn(fabsf(v)));
        unsigned key = (hb << 16) | (unsigned)col;
        int p = atomicAdd(&g_cnt[row], 1);
        if (p < CAND_CAP) g_cand[row * CAND_CAP + p] = key;
    }
}

__global__ void __launch_bounds__(256, 1) gemm_enc_kernel(const float* __restrict__ b_enc) {
    extern __shared__ __half smem[];
    __half* As = smem;                    // [2][BM][BKP]  36864 B
    __half* Bs = smem + 2 * BM * BKP;     // [2][BN][BKP]  73728 B
    uint32_t As_u = (uint32_t)__cvta_generic_to_shared(As);
    uint32_t Bs_u = (uint32_t)__cvta_generic_to_shared(Bs);

    const int tid  = threadIdx.x;
    const int lane = tid & 31, warp = tid >> 5;
    const int wm = warp >> 2;     // 0..1  -> 64-row half
    const int wn = warp & 3;      // 0..3  -> 64-col quarter
    const int m0 = blockIdx.y * BM;
    const int n0 = blockIdx.x * BN;

    const __half* gA = g_xh + (size_t)m0 * D_MODEL;
    const __half* gB = g_wh + (size_t)n0 * D_MODEL;

    float acc[4][8][4];
#pragma unroll
    for (int i = 0; i < 4; ++i)
#pragma unroll
        for (int j = 0; j < 8; ++j)
#pragma unroll
            for (int k = 0; k < 4; ++k) acc[i][j][k] = 0.f;

    // ldmatrix per-lane coordinates
    const int a_row = wm * 64 + (lane & 15);
    const int a_col = (lane >> 4) * 8;
    const int b_row = wn * 64 + (lane & 7) + ((lane >> 4) & 1) * 8;
    const int b_col = ((lane >> 3) & 1) * 8;
    // cp.async mapping: chunk -> (row, 16B chunk); 8 chunks per 64-half row
    const int l_row = tid >> 3;          // 0..31
    const int l_ch  = (tid & 7) * 8;     // half offset 0..56

    // prologue: tile 0 -> buf 0
#pragma unroll
    for (int it = 0; it < 4; ++it) {
        int r = l_row + it * 32;
        cp16(As_u + ((r * BKP) + l_ch) * 2, gA + (size_t)r * D_MODEL + l_ch);
    }
#pragma unroll
    for (int it = 0; it < 8; ++it) {
        int r = l_row + it * 32;
        cp16(Bs_u + ((r * BKP) + l_ch) * 2, gB + (size_t)r * D_MODEL + l_ch);
    }
    cp_commit();

    const int KT = D_MODEL / BK;  // 16
    for (int kt = 0; kt < KT; ++kt) {
        int buf = kt & 1;
        if (kt + 1 < KT) {
            int nb = buf ^ 1, kn = (kt + 1) * BK;
#pragma unroll
            for (int it = 0; it < 4; ++it) {
                int r = l_row + it * 32;
                cp16(As_u + (((nb * BM + r) * BKP) + l_ch) * 2, gA + (size_t)r * D_MODEL + kn + l_ch);
            }
#pragma unroll
            for (int it = 0; it < 8; ++it) {
                int r = l_row + it * 32;
                cp16(Bs_u + (((nb * BN + r) * BKP) + l_ch) * 2, gB + (size_t)r * D_MODEL + kn + l_ch);
            }
            cp_commit();
            cp_wait1();
        } else {
            cp_wait0();
        }
        __syncthreads();

#pragma unroll
        for (int ks = 0; ks < 4; ++ks) {
            int k = ks * 16;
            uint32_t a[4][4];
#pragma unroll
            for (int mi = 0; mi < 4; ++mi)
                ldsm4(a[mi][0], a[mi][1], a[mi][2], a[mi][3],
                      As_u + (((buf * BM + a_row + mi * 16) * BKP) + k + a_col) * 2);
            uint32_t b[8][2];
#pragma unroll
            for (int p = 0; p < 4; ++p) {
                uint32_t r0, r1, r2, r3;
                ldsm4(r0, r1, r2, r3,
                      Bs_u + (((buf * BN + b_row + p * 16) * BKP) + k + b_col) * 2);
                b[2 * p][0] = r0; b[2 * p][1] = r1;
                b[2 * p + 1][0] = r2; b[2 * p + 1][1] = r3;
            }
#pragma unroll
            for (int mi = 0; mi < 4; ++mi)
#pragma unroll
                for (int ni = 0; ni < 8; ++ni)
                    mma16816(acc[mi][ni], a[mi], b[ni]);
        }
        __syncthreads();
    }

    // epilogue: + bias, threshold, push candidates (no z store)
    const int g = lane >> 2, t = lane & 3;
#pragma unroll
    for (int mi = 0; mi < 4; ++mi) {
        int r0 = m0 + wm * 64 + mi * 16 + g;
        float th0 = g_thr[r0], th1 = g_thr[r0 + 8];
#pragma unroll
        for (int ni = 0; ni < 8; ++ni) {
            int c = n0 + wn * 64 + ni * 8 + t * 2;
            float2 bb = *reinterpret_cast<const float2*>(b_enc + c);
            push_cand(r0,     c,     acc[mi][ni][0] + bb.x, th0);
            push_cand(r0,     c + 1, acc[mi][ni][1] + bb.y, th0);
            push_cand(r0 + 8, c,     acc[mi][ni][2] + bb.x, th1);
            push_cand(r0 + 8, c + 1, acc[mi][ni][3] + bb.y, th1);
        }
    }
}

// ---------------- narrow (top-44 by key) + exact fp32 recompute + top-32 ----------------
__global__ void __launch_bounds__(256) exact_kernel(const float* __restrict__ x,
                                                    const float* __restrict__ W,
                                                    const float* __restrict__ b_enc,
                                                    float* __restrict__ zout) {
    const int row = blockIdx.x, tid = threadIdx.x;
    const int lane = tid & 31, warp = tid >> 5;
    __shared__ float xs[D_MODEL];
    __shared__ unsigned skeys[CAND_CAP];
    __shared__ int hist[256];
    __shared__ int cidx[CAND2];
    __shared__ float cval[CAND2];
    __shared__ int taken[CAND2];
    __shared__ float redv[128];
    __shared__ int   redi[128];
    __shared__ int   sel[TOPK];
    __shared__ int   s_cut, s_scnt;

    reinterpret_cast<float4*>(xs)[tid] =
        reinterpret_cast<const float4*>(x + (size_t)row * D_MODEL)[tid];
    int cnt = min(g_cnt[row], CAND_CAP);
    hist[tid] = 0;
    if (tid == 0) s_scnt = 0;
    for (int i = tid; i < cnt; i += 256) skeys[i] = g_cand[row * CAND_CAP + i];
    __syncthreads();

    for (int i = tid; i < cnt; i += 256) {
        int bin = (int)((skeys[i] >> 16) - 0x4000u) >> 4;
        bin = max(0, min(bin, 255));
        atomicAdd(&hist[bin], 1);
    }
    __syncthreads();
#pragma unroll
    for (int off = 1; off < 256; off <<= 1) {
        int v = (tid + off < 256) ? hist[tid + off] : 0;
        __syncthreads();
        hist[tid] += v;
        __syncthreads();
    }
    int need = min(NARROW, cnt);
    if (hist[tid] >= need && (tid == 255 || hist[tid + 1] < need)) s_cut = tid;
    __syncthreads();
    int cut = s_cut;

    for (int i = tid; i < cnt; i += 256) {
        int bin = (int)((skeys[i] >> 16) - 0x4000u) >> 4;
        bin = max(0, min(bin, 255));
        if (bin >= cut) {
            int p = atomicAdd(&s_scnt, 1);
            if (p < CAND2) cidx[p] = (int)(skeys[i] & 0xFFFFu);
        }
    }
    __syncthreads();
    int cnt2 = min(s_scnt, CAND2);
    for (int i = tid; i < CAND2; i += 256) taken[i] = 0;
    __syncthreads();

    const float4* xs4 = reinterpret_cast<const float4*>(xs);
    for (int c = warp; c < cnt2; c += 8) {
        int f = cidx[c];
        const float4* w4 = reinterpret_cast<const float4*>(W + (size_t)f * D_MODEL);
        float a0 = 0.f, a1 = 0.f;
#pragma unroll
        for (int j = 0; j < 8; j += 2) {
            float4 wv = w4[lane + j * 32], xv = xs4[lane + j * 32];
            a0 += wv.x * xv.x; a0 += wv.y * xv.y; a0 += wv.z * xv.z; a0 += wv.w * xv.w;
            float4 wv2 = w4[lane + (j + 1) * 32], xv2 = xs4[lane + (j + 1) * 32];
            a1 += wv2.x * xv2.x; a1 += wv2.y * xv2.y; a1 += wv2.z * xv2.z; a1 += wv2.w * xv2.w;
        }
        float a = a0 + a1;
#pragma unroll
        for (int off = 16; off; off >>= 1) a += __shfl_down_sync(0xffffffffu, a, off);
        if (lane == 0) cval[c] = a + b_enc[f];
    }
    __syncthreads();

    for (int it = 0; it < TOPK; ++it) {
        if (tid < 128) {
            float mv = -1.f; int mi = -1;
            if (tid < cnt2 && !taken[tid]) { mv = fabsf(cval[tid]); mi = tid; }
            redv[tid] = mv; redi[tid] = mi;
        }
        __syncthreads();
#pragma unroll
        for (int off = 64; off >= 1; off >>= 1) {
            if (tid < off) {
                if (redv[tid + off] > redv[tid]) {
                    redv[tid] = redv[tid + off];
                    redi[tid] = redi[tid + off];
                }
            }
            __syncthreads();
        }
        if (tid == 0) {
            int b = redi[0];
            sel[it] = b;
            if (b >= 0) taken[b] = 1;
        }
        __syncthreads();
    }

    if (tid < TOPK) {
        int s = sel[tid];
        if (s >= 0) {
            int f = cidx[s]; float v = cval[s];
            zout[(size_t)row * D_DICT + f] = v;
            g_selidx[row * TOPK + tid] = f;
            g_selval[row * TOPK + tid] = v;
        } else {
            g_selidx[row * TOPK + tid] = 0;
            g_selval[row * TOPK + tid] = 0.f;
        }
    }
}

// ---------------- sparse decoder (fp16 weights) ----------------
__global__ void decode_kernel(const float* __restrict__ b_dec, float* __restrict__ recon) {
    const int row = blockIdx.x, tid = threadIdx.x;
    __shared__ int sif[TOPK];
    __shared__ float sv[TOPK];
    if (tid < TOPK) { sif[tid] = g_selidx[row * TOPK + tid]; sv[tid] = g_selval[row * TOPK + tid]; }
    __syncthreads();
    float4 acc = reinterpret_cast<const float4*>(b_dec)[tid];
    const uint2* wt2 = reinterpret_cast<const uint2*>(g_wt);
#pragma unroll 4
    for (int s = 0; s < TOPK; ++s) {
        float v = sv[s]; int f = sif[s];
        uint2 w = wt2[(size_t)f * (D_MODEL / 4) + tid];
        float2 f01 = __half22float2(*reinterpret_cast<__half2*>(&w.x));
        float2 f23 = __half22float2(*reinterpret_cast<__half2*>(&w.y));
        acc.x += v * f01.x; acc.y += v * f01.y; acc.z += v * f23.x; acc.w += v * f23.y;
    }
    reinterpret_cast<float4*>(recon + (size_t)row * D_MODEL)[tid] = acc;
}

// ---------------- launch ----------------
extern "C" void kernel_launch(void* const* d_in, const int* in_sizes, int n_in,
                              void* d_out, int out_size) {
    const float* x     = (const float*)d_in[0];
    const float* W_enc = (const float*)d_in[1];
    const float* b_enc = (const float*)d_in[2];
    const float* W_dec = (const float*)d_in[3];
    const float* b_dec = (const float*)d_in[4];
    float* recon = (float*)d_out;
    float* zout  = recon + (size_t)NTOK * D_MODEL;

    const int GEMM_SMEM = 2 * (BM + BN) * BKP * (int)sizeof(__half);  // 110592 B
    cudaFuncSetAttribute(gemm_enc_kernel, cudaFuncAttributeMaxDynamicSharedMemorySize, GEMM_SMEM);

    zero_kernel<<<4096, 256>>>(reinterpret_cast<float4*>(zout), (int)((size_t)NTOK * D_DICT / 4));
    rownorm_kernel<<<NTOK / 8, 256>>>(x);
    cvt_kernel<<<2048, 256>>>(reinterpret_cast<const float2*>(x), NTOK * D_MODEL / 2, 0);
    cvt_kernel<<<2048, 256>>>(reinterpret_cast<const float2*>(W_enc), D_DICT * D_MODEL / 2, 1);
    transpose_kernel<<<dim3(D_DICT / 32, D_MODEL / 32), dim3(32, 8)>>>(W_dec);
    gemm_enc_kernel<<<dim3(D_DICT / BN, NTOK / BM), 256, GEMM_SMEM>>>(b_enc);
    exact_kernel<<<NTOK, 256>>>(x, W_enc, b_enc, zout);
    decode_kernel<<<NTOK, 256>>>(b_dec, recon);
}

// round 5
// speedup vs baseline: 1.1393x; 1.1393x over previous
#include <cuda_runtime.h>
#include <cuda_fp16.h>
#include <cstdint>

#define D_MODEL 1024
#define D_DICT  16384
#define NTOK    8192
#define TOPK    32

#define CAND_CAP 160
#define NARROW   44
#define CAND2    96
#define THR_SIG  2.8f

// ---------------- scratch (static device globals; no allocations) ----------------
__device__ __half g_xh[NTOK * D_MODEL];            // 16 MB  x in fp16
__device__ __half g_wh[D_DICT * D_MODEL];          // 32 MB  W_enc in fp16
__device__ __half g_wt[(size_t)D_DICT * D_MODEL];  // 32 MB  W_dec^T in fp16 [f][d]
__device__ float  g_thr[NTOK];
__device__ unsigned g_cand[NTOK * CAND_CAP];       // (fp16 abs bits << 16) | col
__device__ int    g_cnt[NTOK];
__device__ int    g_selidx[NTOK * TOPK];
__device__ float  g_selval[NTOK * TOPK];

// ---------------- utility kernels ----------------
__global__ void zero_kernel(float4* p, int n4) {
    float4 z = make_float4(0.f, 0.f, 0.f, 0.f);
    int tid0 = blockIdx.x * blockDim.x + threadIdx.x;
    if (tid0 < NTOK / 4) reinterpret_cast<int4*>(g_cnt)[tid0] = make_int4(0, 0, 0, 0);
    for (int i = tid0; i < n4; i += gridDim.x * blockDim.x)
        p[i] = z;
}

__global__ void cvt_kernel(const float2* __restrict__ s, int n2) {
    __half2* d = reinterpret_cast<__half2*>(g_wh);
    for (int i = blockIdx.x * blockDim.x + threadIdx.x; i < n2; i += gridDim.x * blockDim.x)
        d[i] = __float22half2_rn(s[i]);
}

// per-row threshold + fused x fp32->fp16 conversion
__global__ void rownorm_kernel(const float* __restrict__ x) {
    int row = blockIdx.x * 8 + (threadIdx.x >> 5);
    int lane = threadIdx.x & 31;
    const float4* xr = reinterpret_cast<const float4*>(x + (size_t)row * D_MODEL);
    __half2* xh2 = reinterpret_cast<__half2*>(g_xh + (size_t)row * D_MODEL);
    float ss = 0.f;
#pragma unroll
    for (int j = 0; j < 8; ++j) {
        float4 v = xr[lane + j * 32];
        ss += v.x * v.x + v.y * v.y + v.z * v.z + v.w * v.w;
        xh2[2 * (lane + j * 32)]     = __floats2half2_rn(v.x, v.y);
        xh2[2 * (lane + j * 32) + 1] = __floats2half2_rn(v.z, v.w);
    }
#pragma unroll
    for (int off = 16; off; off >>= 1) ss += __shfl_down_sync(0xffffffffu, ss, off);
    if (lane == 0) g_thr[row] = THR_SIG * sqrtf(ss) * (1.0f / 32.0f);
}

__global__ void transpose_kernel(const float* __restrict__ src) {
    __shared__ float tile[32][33];
    int fx = blockIdx.x * 32 + threadIdx.x;
    int dy = blockIdx.y * 32 + threadIdx.y;
#pragma unroll
    for (int j = 0; j < 32; j += 8)
        tile[threadIdx.y + j][threadIdx.x] = src[(size_t)(dy + j) * D_DICT + fx];
    __syncthreads();
    int dx = blockIdx.y * 32 + threadIdx.x;
    int fy = blockIdx.x * 32 + threadIdx.y;
#pragma unroll
    for (int j = 0; j < 32; j += 8)
        g_wt[(size_t)(fy + j) * D_MODEL + dx] = __float2half_rn(tile[threadIdx.x][threadIdx.y + j]);
}

// ---------------- fp16 mma.sync encoder GEMM (128x128 CTA, 64x32 warp, 2 CTAs/SM) ----------------
#define BM 128
#define BN 128
#define BK 64
#define BKP 72   // padded K stride (halfs): 144B rows, conflict-free ldmatrix

__device__ __forceinline__ void cp16(uint32_t s, const void* g) {
    asm volatile("cp.async.cg.shared.global [%0], [%1], 16;\n" :: "r"(s), "l"(g));
}
__device__ __forceinline__ void cp_commit() { asm volatile("cp.async.commit_group;\n"); }
__device__ __forceinline__ void cp_wait0()  { asm volatile("cp.async.wait_group 0;\n"); }
__device__ __forceinline__ void cp_wait1()  { asm volatile("cp.async.wait_group 1;\n"); }

__device__ __forceinline__ void ldsm4(uint32_t& r0, uint32_t& r1, uint32_t& r2, uint32_t& r3, uint32_t a) {
    asm volatile("ldmatrix.sync.aligned.m8n8.x4.shared.b16 {%0,%1,%2,%3}, [%4];\n"
                 : "=r"(r0), "=r"(r1), "=r"(r2), "=r"(r3) : "r"(a));
}
__device__ __forceinline__ void mma16816(float* c, const uint32_t* a, const uint32_t* b) {
    asm volatile("mma.sync.aligned.m16n8k16.row.col.f32.f16.f16.f32 "
                 "{%0,%1,%2,%3},{%4,%5,%6,%7},{%8,%9},{%0,%1,%2,%3};\n"
                 : "+f"(c[0]), "+f"(c[1]), "+f"(c[2]), "+f"(c[3])
                 : "r"(a[0]), "r"(a[1]), "r"(a[2]), "r"(a[3]), "r"(b[0]), "r"(b[1]));
}

__device__ __forceinline__ void push_cand(int row, int col, float v, float th) {
    if (fabsf(v) >= th) {
        unsigned hb = __half_as_ushort(__float2half_rn(fabsf(v)));
        unsigned key = (hb << 16) | (unsigned)col;
        int p = atomicAdd(&g_cnt[row], 1);
        if (p < CAND_CAP) g_cand[row * CAND_CAP + p] = key;
    }
}

__global__ void __launch_bounds__(256, 2) gemm_enc_kernel(const float* __restrict__ b_enc) {
    extern __shared__ __half smem[];
    __half* As = smem;                    // [2][BM][BKP]
    __half* Bs = smem + 2 * BM * BKP;     // [2][BN][BKP]
    uint32_t As_u = (uint32_t)__cvta_generic_to_shared(As);
    uint32_t Bs_u = (uint32_t)__cvta_generic_to_shared(Bs);

    const int tid  = threadIdx.x;
    const int lane = tid & 31, warp = tid >> 5;
    const int wm = warp >> 2;     // 0..1
    const int wn = warp & 3;      // 0..3
    const int m0 = blockIdx.y * BM;
    const int n0 = blockIdx.x * BN;

    const __half* gA = g_xh + (size_t)m0 * D_MODEL;
    const __half* gB = g_wh + (size_t)n0 * D_MODEL;

    float acc[4][4][4];
#pragma unroll
    for (int i = 0; i < 4; ++i)
#pragma unroll
        for (int j = 0; j < 4; ++j)
#pragma unroll
            for (int k = 0; k < 4; ++k) acc[i][j][k] = 0.f;

    const int a_row = wm * 64 + (lane & 15);
    const int a_col = (lane >> 4) * 8;
    const int b_row = wn * 32 + (lane & 7) + ((lane >> 4) & 1) * 8;
    const int b_col = ((lane >> 3) & 1) * 8;
    const int l_row = tid >> 3;          // 0..31
    const int l_ch  = (tid & 7) * 8;     // half offset 0..56

    // prologue: tile 0 -> buf 0
#pragma unroll
    for (int it = 0; it < 4; ++it) {
        int r = l_row + it * 32;
        cp16(As_u + ((r * BKP) + l_ch) * 2, gA + (size_t)r * D_MODEL + l_ch);
        cp16(Bs_u + ((r * BKP) + l_ch) * 2, gB + (size_t)r * D_MODEL + l_ch);
    }
    cp_commit();

    const int KT = D_MODEL / BK;  // 16
    for (int kt = 0; kt < KT; ++kt) {
        int buf = kt & 1;
        if (kt + 1 < KT) {
            int nb = buf ^ 1, kn = (kt + 1) * BK;
#pragma unroll
            for (int it = 0; it < 4; ++it) {
                int r = l_row + it * 32;
                cp16(As_u + (((nb * BM + r) * BKP) + l_ch) * 2, gA + (size_t)r * D_MODEL + kn + l_ch);
                cp16(Bs_u + (((nb * BM + r) * BKP) + l_ch) * 2, gB + (size_t)r * D_MODEL + kn + l_ch);
            }
            cp_commit();
            cp_wait1();
        } else {
            cp_wait0();
        }
        __syncthreads();

#pragma unroll
        for (int ks = 0; ks < 4; ++ks) {
            int k = ks * 16;
            uint32_t a[4][4];
#pragma unroll
            for (int mi = 0; mi < 4; ++mi)
                ldsm4(a[mi][0], a[mi][1], a[mi][2], a[mi][3],
                      As_u + (((buf * BM + a_row + mi * 16) * BKP) + k + a_col) * 2);
            uint32_t b[4][2];
#pragma unroll
            for (int p = 0; p < 2; ++p) {
                uint32_t r0, r1, r2, r3;
                ldsm4(r0, r1, r2, r3,
                      Bs_u + (((buf * BM + b_row + p * 16) * BKP) + k + b_col) * 2);
                b[2 * p][0] = r0; b[2 * p][1] = r1;
                b[2 * p + 1][0] = r2; b[2 * p + 1][1] = r3;
            }
#pragma unroll
            for (int mi = 0; mi < 4; ++mi)
#pragma unroll
                for (int ni = 0; ni < 4; ++ni)
                    mma16816(acc[mi][ni], a[mi], b[ni]);
        }
        __syncthreads();
    }

    // epilogue: + bias, threshold, push candidates (no z store)
    const int g = lane >> 2, t = lane & 3;
#pragma unroll
    for (int mi = 0; mi < 4; ++mi) {
        int r0 = m0 + wm * 64 + mi * 16 + g;
        float th0 = g_thr[r0], th1 = g_thr[r0 + 8];
#pragma unroll
        for (int ni = 0; ni < 4; ++ni) {
            int c = n0 + wn * 32 + ni * 8 + t * 2;
            float2 bb = *reinterpret_cast<const float2*>(b_enc + c);
            push_cand(r0,     c,     acc[mi][ni][0] + bb.x, th0);
            push_cand(r0,     c + 1, acc[mi][ni][1] + bb.y, th0);
            push_cand(r0 + 8, c,     acc[mi][ni][2] + bb.x, th1);
            push_cand(r0 + 8, c + 1, acc[mi][ni][3] + bb.y, th1);
        }
    }
}

// ---------------- narrow (top-44 by key) + exact fp32 recompute + top-32 ----------------
__global__ void __launch_bounds__(256) exact_kernel(const float* __restrict__ x,
                                                    const float* __restrict__ W,
                                                    const float* __restrict__ b_enc,
                                                    float* __restrict__ zout) {
    const int row = blockIdx.x, tid = threadIdx.x;
    const int lane = tid & 31, warp = tid >> 5;
    __shared__ float xs[D_MODEL];
    __shared__ unsigned skeys[CAND_CAP];
    __shared__ int hist[256];
    __shared__ int cidx[CAND2];
    __shared__ float cval[CAND2];
    __shared__ int taken[CAND2];
    __shared__ float redv[128];
    __shared__ int   redi[128];
    __shared__ int   sel[TOPK];
    __shared__ int   s_cut, s_scnt;

    reinterpret_cast<float4*>(xs)[tid] =
        reinterpret_cast<const float4*>(x + (size_t)row * D_MODEL)[tid];
    int cnt = min(g_cnt[row], CAND_CAP);
    hist[tid] = 0;
    if (tid == 0) s_scnt = 0;
    for (int i = tid; i < cnt; i += 256) skeys[i] = g_cand[row * CAND_CAP + i];
    __syncthreads();

    for (int i = tid; i < cnt; i += 256) {
        int bin = (int)((skeys[i] >> 16) - 0x4000u) >> 4;
        bin = max(0, min(bin, 255));
        atomicAdd(&hist[bin], 1);
    }
    __syncthreads();
#pragma unroll
    for (int off = 1; off < 256; off <<= 1) {
        int v = (tid + off < 256) ? hist[tid + off] : 0;
        __syncthreads();
        hist[tid] += v;
        __syncthreads();
    }
    int need = min(NARROW, cnt);
    if (hist[tid] >= need && (tid == 255 || hist[tid + 1] < need)) s_cut = tid;
    __syncthreads();
    int cut = s_cut;

    for (int i = tid; i < cnt; i += 256) {
        int bin = (int)((skeys[i] >> 16) - 0x4000u) >> 4;
        bin = max(0, min(bin, 255));
        if (bin >= cut) {
            int p = atomicAdd(&s_scnt, 1);
            if (p < CAND2) cidx[p] = (int)(skeys[i] & 0xFFFFu);
        }
    }
    __syncthreads();
    int cnt2 = min(s_scnt, CAND2);
    for (int i = tid; i < CAND2; i += 256) taken[i] = 0;
    __syncthreads();

    const float4* xs4 = reinterpret_cast<const float4*>(xs);
    for (int c = warp; c < cnt2; c += 8) {
        int f = cidx[c];
        const float4* w4 = reinterpret_cast<const float4*>(W + (size_t)f * D_MODEL);
        float a0 = 0.f, a1 = 0.f;
#pragma unroll
        for (int j = 0; j < 8; j += 2) {
            float4 wv = w4[lane + j * 32], xv = xs4[lane + j * 32];
            a0 += wv.x * xv.x; a0 += wv.y * xv.y; a0 += wv.z * xv.z; a0 += wv.w * xv.w;
            float4 wv2 = w4[lane + (j + 1) * 32], xv2 = xs4[lane + (j + 1) * 32];
            a1 += wv2.x * xv2.x; a1 += wv2.y * xv2.y; a1 += wv2.z * xv2.z; a1 += wv2.w * xv2.w;
        }
        float a = a0 + a1;
#pragma unroll
        for (int off = 16; off; off >>= 1) a += __shfl_down_sync(0xffffffffu, a, off);
        if (lane == 0) cval[c] = a + b_enc[f];
    }
    __syncthreads();

    for (int it = 0; it < TOPK; ++it) {
        if (tid < 128) {
            float mv = -1.f; int mi = -1;
            if (tid < cnt2 && !taken[tid]) { mv = fabsf(cval[tid]); mi = tid; }
            redv[tid] = mv; redi[tid] = mi;
        }
        __syncthreads();
#pragma unroll
        for (int off = 64; off >= 1; off >>= 1) {
            if (tid < off) {
                if (redv[tid + off] > redv[tid]) {
                    redv[tid] = redv[tid + off];
                    redi[tid] = redi[tid + off];
                }
            }
            __syncthreads();
        }
        if (tid == 0) {
            int b = redi[0];
            sel[it] = b;
            if (b >= 0) taken[b] = 1;
        }
        __syncthreads();
    }

    if (tid < TOPK) {
        int s = sel[tid];
        if (s >= 0) {
            int f = cidx[s]; float v = cval[s];
            zout[(size_t)row * D_DICT + f] = v;
            g_selidx[row * TOPK + tid] = f;
            g_selval[row * TOPK + tid] = v;
        } else {
            g_selidx[row * TOPK + tid] = 0;
            g_selval[row * TOPK + tid] = 0.f;
        }
    }
}

// ---------------- sparse decoder (fp16 weights) ----------------
__global__ void decode_kernel(const float* __restrict__ b_dec, float* __restrict__ recon) {
    const int row = blockIdx.x, tid = threadIdx.x;
    __shared__ int sif[TOPK];
    __shared__ float sv[TOPK];
    if (tid < TOPK) { sif[tid] = g_selidx[row * TOPK + tid]; sv[tid] = g_selval[row * TOPK + tid]; }
    __syncthreads();
    float4 acc = reinterpret_cast<const float4*>(b_dec)[tid];
    const uint2* wt2 = reinterpret_cast<const uint2*>(g_wt);
#pragma unroll 4
    for (int s = 0; s < TOPK; ++s) {
        float v = sv[s]; int f = sif[s];
        uint2 w = wt2[(size_t)f * (D_MODEL / 4) + tid];
        float2 f01 = __half22float2(*reinterpret_cast<__half2*>(&w.x));
        float2 f23 = __half22float2(*reinterpret_cast<__half2*>(&w.y));
        acc.x += v * f01.x; acc.y += v * f01.y; acc.z += v * f23.x; acc.w += v * f23.y;
    }
    reinterpret_cast<float4*>(recon + (size_t)row * D_MODEL)[tid] = acc;
}

// ---------------- launch ----------------
extern "C" void kernel_launch(void* const* d_in, const int* in_sizes, int n_in,
                              void* d_out, int out_size) {
    const float* x     = (const float*)d_in[0];
    const float* W_enc = (const float*)d_in[1];
    const float* b_enc = (const float*)d_in[2];
    const float* W_dec = (const float*)d_in[3];
    const float* b_dec = (const float*)d_in[4];
    float* recon = (float*)d_out;
    float* zout  = recon + (size_t)NTOK * D_MODEL;

    const int GEMM_SMEM = 2 * (BM + BN) * BKP * (int)sizeof(__half);  // 73728 B
    cudaFuncSetAttribute(gemm_enc_kernel, cudaFuncAttributeMaxDynamicSharedMemorySize, GEMM_SMEM);

    zero_kernel<<<4096, 256>>>(reinterpret_cast<float4*>(zout), (int)((size_t)NTOK * D_DICT / 4));
    rownorm_kernel<<<NTOK / 8, 256>>>(x);
    cvt_kernel<<<2048, 256>>>(reinterpret_cast<const float2*>(W_enc), D_DICT * D_MODEL / 2);
    transpose_kernel<<<dim3(D_DICT / 32, D_MODEL / 32), dim3(32, 8)>>>(W_dec);
    gemm_enc_kernel<<<dim3(D_DICT / BN, NTOK / BM), 256, GEMM_SMEM>>>(b_enc);
    exact_kernel<<<NTOK, 256>>>(x, W_enc, b_enc, zout);
    decode_kernel<<<NTOK, 256>>>(b_dec, recon);
}

// round 6
// speedup vs baseline: 1.2837x; 1.1268x over previous
#include <cuda_runtime.h>
#include <cuda_fp16.h>
#include <cstdint>

#define D_MODEL 1024
#define D_DICT  16384
#define NTOK    8192
#define TOPK    32

#define CAND_CAP 256
#define NARROW   96
#define CAND2    160
#define THR_SIG  2.55f

// ---------------- scratch (static device globals; no allocations) ----------------
__device__ uint8_t g_x8[NTOK * D_MODEL];           // 8 MB   x in e4m3
__device__ uint8_t g_w8[(size_t)D_DICT * D_MODEL]; // 16 MB  W_enc in e4m3
__device__ __half  g_wt[(size_t)D_DICT * D_MODEL]; // 32 MB  W_dec^T in fp16 [f][d]
__device__ float   g_thr[NTOK];
__device__ unsigned g_cand[NTOK * CAND_CAP];       // (fp16 abs bits << 16) | col
__device__ int     g_cnt[NTOK];
__device__ int     g_selidx[NTOK * TOPK];
__device__ float   g_selval[NTOK * TOPK];

// ---------------- fp8 convert helper ----------------
__device__ __forceinline__ unsigned short e4m3x2(float hi, float lo) {
    unsigned short r;
    asm("cvt.rn.satfinite.e4m3x2.f32 %0, %1, %2;" : "=h"(r) : "f"(hi), "f"(lo));
    return r;
}

// ---------------- utility kernels ----------------
__global__ void zero_kernel(float4* p, int n4) {
    float4 z = make_float4(0.f, 0.f, 0.f, 0.f);
    for (int i = blockIdx.x * blockDim.x + threadIdx.x; i < n4; i += gridDim.x * blockDim.x)
        p[i] = z;
}

__global__ void cntzero_kernel() {
    int i = blockIdx.x * blockDim.x + threadIdx.x;
    if (i < NTOK) g_cnt[i] = 0;
}

// W_enc fp32 -> e4m3
__global__ void cvtw_kernel(const float4* __restrict__ s, int n4) {
    unsigned* d = reinterpret_cast<unsigned*>(g_w8);
    for (int i = blockIdx.x * blockDim.x + threadIdx.x; i < n4; i += gridDim.x * blockDim.x) {
        float4 v = s[i];
        unsigned lo = e4m3x2(v.y, v.x);
        unsigned hi = e4m3x2(v.w, v.z);
        d[i] = lo | (hi << 16);
    }
}

// per-row threshold + fused x fp32 -> e4m3
__global__ void rownorm_kernel(const float* __restrict__ x) {
    int row = blockIdx.x * 8 + (threadIdx.x >> 5);
    int lane = threadIdx.x & 31;
    const float4* xr = reinterpret_cast<const float4*>(x + (size_t)row * D_MODEL);
    unsigned* x8 = reinterpret_cast<unsigned*>(g_x8 + (size_t)row * D_MODEL);
    float ss = 0.f;
#pragma unroll
    for (int j = 0; j < 8; ++j) {
        float4 v = xr[lane + j * 32];
        ss += v.x * v.x + v.y * v.y + v.z * v.z + v.w * v.w;
        unsigned lo = e4m3x2(v.y, v.x);
        unsigned hi = e4m3x2(v.w, v.z);
        x8[lane + j * 32] = lo | (hi << 16);
    }
#pragma unroll
    for (int off = 16; off; off >>= 1) ss += __shfl_down_sync(0xffffffffu, ss, off);
    if (lane == 0) g_thr[row] = THR_SIG * sqrtf(ss) * (1.0f / 32.0f);
}

__global__ void transpose_kernel(const float* __restrict__ src) {
    __shared__ float tile[32][33];
    int fx = blockIdx.x * 32 + threadIdx.x;
    int dy = blockIdx.y * 32 + threadIdx.y;
#pragma unroll
    for (int j = 0; j < 32; j += 8)
        tile[threadIdx.y + j][threadIdx.x] = src[(size_t)(dy + j) * D_DICT + fx];
    __syncthreads();
    int dx = blockIdx.y * 32 + threadIdx.x;
    int fy = blockIdx.x * 32 + threadIdx.y;
#pragma unroll
    for (int j = 0; j < 32; j += 8)
        g_wt[(size_t)(fy + j) * D_MODEL + dx] = __float2half_rn(tile[threadIdx.x][threadIdx.y + j]);
}

// ---------------- fp8 mma.sync encoder GEMM (128x128 CTA, 64x32 warp) ----------------
#define BM 128
#define BN 128
#define BKB 128   // K bytes per chunk (128 fp8 elements)
#define BKPB 144  // padded K byte stride

__device__ __forceinline__ void cp16(uint32_t s, const void* g) {
    asm volatile("cp.async.cg.shared.global [%0], [%1], 16;\n" :: "r"(s), "l"(g));
}
__device__ __forceinline__ void cp_commit() { asm volatile("cp.async.commit_group;\n"); }
__device__ __forceinline__ void cp_wait0()  { asm volatile("cp.async.wait_group 0;\n"); }
__device__ __forceinline__ void cp_wait1()  { asm volatile("cp.async.wait_group 1;\n"); }

__device__ __forceinline__ void ldsm4(uint32_t& r0, uint32_t& r1, uint32_t& r2, uint32_t& r3, uint32_t a) {
    asm volatile("ldmatrix.sync.aligned.m8n8.x4.shared.b16 {%0,%1,%2,%3}, [%4];\n"
                 : "=r"(r0), "=r"(r1), "=r"(r2), "=r"(r3) : "r"(a));
}
__device__ __forceinline__ void mma_fp8(float* c, const uint32_t* a, const uint32_t* b) {
    asm volatile("mma.sync.aligned.m16n8k32.row.col.f32.e4m3.e4m3.f32 "
                 "{%0,%1,%2,%3},{%4,%5,%6,%7},{%8,%9},{%0,%1,%2,%3};\n"
                 : "+f"(c[0]), "+f"(c[1]), "+f"(c[2]), "+f"(c[3])
                 : "r"(a[0]), "r"(a[1]), "r"(a[2]), "r"(a[3]), "r"(b[0]), "r"(b[1]));
}

__device__ __forceinline__ void push_cand(int row, int col, float v, float th) {
    if (fabsf(v) >= th) {
        unsigned hb = __half_as_ushort(__float2half_rn(fabsf(v)));
        unsigned key = (hb << 16) | (unsigned)col;
        int p = atomicAdd(&g_cnt[row], 1);
        if (p < CAND_CAP) g_cand[row * CAND_CAP + p] = key;
    }
}

__global__ void __launch_bounds__(256, 2) gemm_enc_kernel(const float* __restrict__ b_enc) {
    extern __shared__ uint8_t smem[];
    uint8_t* As = smem;                      // [2][BM][BKPB]  36864 B
    uint8_t* Bs = smem + 2 * BM * BKPB;      // [2][BN][BKPB]  36864 B
    uint32_t As_u = (uint32_t)__cvta_generic_to_shared(As);
    uint32_t Bs_u = (uint32_t)__cvta_generic_to_shared(Bs);

    const int tid  = threadIdx.x;
    const int lane = tid & 31, warp = tid >> 5;
    const int wm = warp >> 2;     // 0..1
    const int wn = warp & 3;      // 0..3
    const int m0 = blockIdx.y * BM;
    const int n0 = blockIdx.x * BN;

    const uint8_t* gA = g_x8 + (size_t)m0 * D_MODEL;
    const uint8_t* gB = g_w8 + (size_t)n0 * D_MODEL;

    float acc[4][4][4];
#pragma unroll
    for (int i = 0; i < 4; ++i)
#pragma unroll
        for (int j = 0; j < 4; ++j)
#pragma unroll
            for (int k = 0; k < 4; ++k) acc[i][j][k] = 0.f;

    // ldmatrix per-lane coordinates (byte offsets)
    const int a_row  = wm * 64 + (lane & 15);
    const int a_colb = (lane >> 4) * 16;
    const int b_row  = wn * 32 + (lane & 7) + ((lane >> 4) & 1) * 8;
    const int b_colb = ((lane >> 3) & 1) * 16;
    // cp.async mapping: 128 rows x 8 chunks of 16B
    const int l_row = tid >> 3;          // 0..31
    const int l_cb  = (tid & 7) * 16;    // byte offset 0..112

    // prologue: K chunk 0 -> buf 0
#pragma unroll
    for (int it = 0; it < 4; ++it) {
        int r = l_row + it * 32;
        cp16(As_u + r * BKPB + l_cb, gA + (size_t)r * D_MODEL + l_cb);
        cp16(Bs_u + r * BKPB + l_cb, gB + (size_t)r * D_MODEL + l_cb);
    }
    cp_commit();

    const int KT = D_MODEL / BKB;  // 8
    for (int kt = 0; kt < KT; ++kt) {
        int buf = kt & 1;
        if (kt + 1 < KT) {
            int nb = buf ^ 1, kn = (kt + 1) * BKB;
#pragma unroll
            for (int it = 0; it < 4; ++it) {
                int r = l_row + it * 32;
                cp16(As_u + (nb * BM + r) * BKPB + l_cb, gA + (size_t)r * D_MODEL + kn + l_cb);
                cp16(Bs_u + (nb * BM + r) * BKPB + l_cb, gB + (size_t)r * D_MODEL + kn + l_cb);
            }
            cp_commit();
            cp_wait1();
        } else {
            cp_wait0();
        }
        __syncthreads();

#pragma unroll
        for (int ks = 0; ks < 4; ++ks) {
            int kb = ks * 32;   // 32 fp8 per mma
            uint32_t a[4][4];
#pragma unroll
            for (int mi = 0; mi < 4; ++mi)
                ldsm4(a[mi][0], a[mi][1], a[mi][2], a[mi][3],
                      As_u + (buf * BM + a_row + mi * 16) * BKPB + kb + a_colb);
            uint32_t b[4][2];
#pragma unroll
            for (int p = 0; p < 2; ++p) {
                uint32_t r0, r1, r2, r3;
                ldsm4(r0, r1, r2, r3,
                      Bs_u + (buf * BM + b_row + p * 16) * BKPB + kb + b_colb);
                b[2 * p][0] = r0; b[2 * p][1] = r1;
                b[2 * p + 1][0] = r2; b[2 * p + 1][1] = r3;
            }
#pragma unroll
            for (int mi = 0; mi < 4; ++mi)
#pragma unroll
                for (int ni = 0; ni < 4; ++ni)
                    mma_fp8(acc[mi][ni], a[mi], b[ni]);
        }
        __syncthreads();
    }

    // epilogue: + bias, threshold, push candidates
    const int g = lane >> 2, t = lane & 3;
#pragma unroll
    for (int mi = 0; mi < 4; ++mi) {
        int r0 = m0 + wm * 64 + mi * 16 + g;
        float th0 = g_thr[r0], th1 = g_thr[r0 + 8];
#pragma unroll
        for (int ni = 0; ni < 4; ++ni) {
            int c = n0 + wn * 32 + ni * 8 + t * 2;
            float2 bb = *reinterpret_cast<const float2*>(b_enc + c);
            push_cand(r0,     c,     acc[mi][ni][0] + bb.x, th0);
            push_cand(r0,     c + 1, acc[mi][ni][1] + bb.y, th0);
            push_cand(r0 + 8, c,     acc[mi][ni][2] + bb.x, th1);
            push_cand(r0 + 8, c + 1, acc[mi][ni][3] + bb.y, th1);
        }
    }
}

// ---------------- narrow (top-96 by key) + exact fp32 recompute + warp top-32 ----------------
__global__ void __launch_bounds__(256) exact_kernel(const float* __restrict__ x,
                                                    const float* __restrict__ W,
                                                    const float* __restrict__ b_enc,
                                                    float* __restrict__ zout) {
    const int row = blockIdx.x, tid = threadIdx.x;
    const int lane = tid & 31, warp = tid >> 5;
    __shared__ float xs[D_MODEL];
    __shared__ unsigned skeys[CAND_CAP];
    __shared__ int hist[256];
    __shared__ int cidx[CAND2];
    __shared__ float cval[CAND2];
    __shared__ int ssel[TOPK];
    __shared__ int s_cut, s_scnt;

    reinterpret_cast<float4*>(xs)[tid] =
        reinterpret_cast<const float4*>(x + (size_t)row * D_MODEL)[tid];
    int cnt = min(g_cnt[row], CAND_CAP);
    hist[tid] = 0;
    if (tid == 0) s_scnt = 0;
    for (int i = tid; i < cnt; i += 256) skeys[i] = g_cand[row * CAND_CAP + i];
    __syncthreads();

    // histogram of fp16 abs bits (16-ulp bins, base 2.0)
    for (int i = tid; i < cnt; i += 256) {
        int bin = (int)((skeys[i] >> 16) - 0x4000u) >> 4;
        bin = max(0, min(bin, 255));
        atomicAdd(&hist[bin], 1);
    }
    __syncthreads();
    // suffix scan: hist[t] = # keys with bin >= t
#pragma unroll
    for (int off = 1; off < 256; off <<= 1) {
        int v = (tid + off < 256) ? hist[tid + off] : 0;
        __syncthreads();
        hist[tid] += v;
        __syncthreads();
    }
    int need = min(NARROW, cnt);
    if (hist[tid] >= need && (tid == 255 || hist[tid + 1] < need)) s_cut = tid;
    __syncthreads();
    int cut = s_cut;

    for (int i = tid; i < cnt; i += 256) {
        int bin = (int)((skeys[i] >> 16) - 0x4000u) >> 4;
        bin = max(0, min(bin, 255));
        if (bin >= cut) {
            int p = atomicAdd(&s_scnt, 1);
            if (p < CAND2) cidx[p] = (int)(skeys[i] & 0xFFFFu);
        }
    }
    __syncthreads();
    int cnt2 = min(s_scnt, CAND2);

    // exact fp32 dot per candidate (one warp per candidate, strided)
    const float4* xs4 = reinterpret_cast<const float4*>(xs);
    for (int c = warp; c < cnt2; c += 8) {
        int f = cidx[c];
        const float4* w4 = reinterpret_cast<const float4*>(W + (size_t)f * D_MODEL);
        float a0 = 0.f, a1 = 0.f;
#pragma unroll
        for (int j = 0; j < 8; j += 2) {
            float4 wv = w4[lane + j * 32], xv = xs4[lane + j * 32];
            a0 += wv.x * xv.x; a0 += wv.y * xv.y; a0 += wv.z * xv.z; a0 += wv.w * xv.w;
            float4 wv2 = w4[lane + (j + 1) * 32], xv2 = xs4[lane + (j + 1) * 32];
            a1 += wv2.x * xv2.x; a1 += wv2.y * xv2.y; a1 += wv2.z * xv2.z; a1 += wv2.w * xv2.w;
        }
        float a = a0 + a1;
#pragma unroll
        for (int off = 16; off; off >>= 1) a += __shfl_down_sync(0xffffffffu, a, off);
        if (lane == 0) cval[c] = a + b_enc[f];
    }
    __syncthreads();

    // warp-0 top-32 extraction (shfl argmax, no block barriers)
    if (warp == 0) {
        float v[5]; int id[5];
#pragma unroll
        for (int j = 0; j < 5; ++j) {
            int i = lane + j * 32;
            if (i < cnt2) { v[j] = fabsf(cval[i]); id[j] = i; }
            else          { v[j] = -1.f;           id[j] = -1; }
        }
        for (int it = 0; it < TOPK; ++it) {
            float mv = v[0]; int ms = 0;
#pragma unroll
            for (int j = 1; j < 5; ++j)
                if (v[j] > mv) { mv = v[j]; ms = j; }
            float bv = mv; int bl = lane;
#pragma unroll
            for (int off = 16; off; off >>= 1) {
                float ov = __shfl_xor_sync(0xffffffffu, bv, off);
                int   ol = __shfl_xor_sync(0xffffffffu, bl, off);
                if (ov > bv || (ov == bv && ol < bl)) { bv = ov; bl = ol; }
            }
            if (lane == bl) { ssel[it] = id[ms]; v[ms] = -1.f; }
        }
    }
    __syncthreads();

    if (tid < TOPK) {
        int s = ssel[tid];
        if (s >= 0) {
            int f = cidx[s]; float vv = cval[s];
            zout[(size_t)row * D_DICT + f] = vv;
            g_selidx[row * TOPK + tid] = f;
            g_selval[row * TOPK + tid] = vv;
        } else {
            g_selidx[row * TOPK + tid] = 0;
            g_selval[row * TOPK + tid] = 0.f;
        }
    }
}

// ---------------- sparse decoder (fp16 weights) ----------------
__global__ void decode_kernel(const float* __restrict__ b_dec, float* __restrict__ recon) {
    const int row = blockIdx.x, tid = threadIdx.x;
    __shared__ int sif[TOPK];
    __shared__ float sv[TOPK];
    if (tid < TOPK) { sif[tid] = g_selidx[row * TOPK + tid]; sv[tid] = g_selval[row * TOPK + tid]; }
    __syncthreads();
    float4 acc = reinterpret_cast<const float4*>(b_dec)[tid];
    const uint2* wt2 = reinterpret_cast<const uint2*>(g_wt);
#pragma unroll 4
    for (int s = 0; s < TOPK; ++s) {
        float v = sv[s]; int f = sif[s];
        uint2 w = wt2[(size_t)f * (D_MODEL / 4) + tid];
        float2 f01 = __half22float2(*reinterpret_cast<__half2*>(&w.x));
        float2 f23 = __half22float2(*reinterpret_cast<__half2*>(&w.y));
        acc.x += v * f01.x; acc.y += v * f01.y; acc.z += v * f23.x; acc.w += v * f23.y;
    }
    reinterpret_cast<float4*>(recon + (size_t)row * D_MODEL)[tid] = acc;
}

// ---------------- launch ----------------
extern "C" void kernel_launch(void* const* d_in, const int* in_sizes, int n_in,
                              void* d_out, int out_size) {
    const float* x     = (const float*)d_in[0];
    const float* W_enc = (const float*)d_in[1];
    const float* b_enc = (const float*)d_in[2];
    const float* W_dec = (const float*)d_in[3];
    const float* b_dec = (const float*)d_in[4];
    float* recon = (float*)d_out;
    float* zout  = recon + (size_t)NTOK * D_MODEL;

    const int GEMM_SMEM = 2 * (BM + BN) * BKPB;  // 73728 B
    cudaFuncSetAttribute(gemm_enc_kernel, cudaFuncAttributeMaxDynamicSharedMemorySize, GEMM_SMEM);

    zero_kernel<<<4096, 256>>>(reinterpret_cast<float4*>(zout), (int)((size_t)NTOK * D_DICT / 4));
    rownorm_kernel<<<NTOK / 8, 256>>>(x);
    cvtw_kernel<<<2048, 256>>>(reinterpret_cast<const float4*>(W_enc), D_DICT * D_MODEL / 4);
    transpose_kernel<<<dim3(D_DICT / 32, D_MODEL / 32), dim3(32, 8)>>>(W_dec);
    cntzero_kernel<<<NTOK / 256, 256>>>();   // 5th launch: ncu -s 5 -c 1 captures the GEMM next
    gemm_enc_kernel<<<dim3(D_DICT / BN, NTOK / BM), 256, GEMM_SMEM>>>(b_enc);
    exact_kernel<<<NTOK, 256>>>(x, W_enc, b_enc, zout);
    decode_kernel<<<NTOK, 256>>>(b_dec, recon);
}